// round 4
// baseline (speedup 1.0000x reference)
#include <cuda_runtime.h>
#include <cuda_bf16.h>

#define F 128
#define MAXN 50048

#define BM 64
#define BN 128
#define BK 16

// Device-global scratch. Never referenced from host code; all atomics target
// these buffers only. 16B-aligned for float4 access.
__device__ __align__(16) float g_h[(size_t)MAXN * F];     // GEMM out / scatter src
__device__ __align__(16) float g_out1[(size_t)MAXN * F];  // layer-1 aggregation
__device__ __align__(16) float g_out2[(size_t)MAXN * F];  // layer-2 aggregation
__device__ float g_dinv[MAXN];
__device__ int   g_deg[MAXN];
__device__ int   g_is64;   // 1 if edge_index arrived as int64, 0 if int32

// ---------------------------------------------------------------------------
// dtype detection: int64 little-endian => odd int32 words of first 64 entries
// are the (zero) high halves. int32 edge list => they are random node ids.
// ---------------------------------------------------------------------------
__global__ void detect_kernel(const int* __restrict__ ei32) {
    if (blockIdx.x == 0 && threadIdx.x == 0) {
        int is64 = 1;
        for (int k = 1; k < 128; k += 2)
            if (ei32[k] != 0) { is64 = 0; break; }
        g_is64 = is64;
    }
}

__device__ __forceinline__ int edge_at(const int* __restrict__ ei32,
                                       long long idx, int is64) {
    if (is64) return (int)__ldg(((const long long*)ei32) + idx);
    return __ldg(ei32 + idx);
}

// ---------------------------------------------------------------------------
// degree / normalization
// ---------------------------------------------------------------------------
__global__ void zero_deg_kernel(int N) {
    int i = blockIdx.x * blockDim.x + threadIdx.x;
    if (i < N) g_deg[i] = 0;
}

__global__ void count_deg_kernel(const int* __restrict__ ei, int E, int N) {
    int e = blockIdx.x * blockDim.x + threadIdx.x;
    if (e < E) {
        int is64 = g_is64;
        int dst = edge_at(ei, (long long)E + e, is64);
        if ((unsigned)dst < (unsigned)N)   // guard: never issue a wild atomic
            atomicAdd(&g_deg[dst], 1);
    }
}

__global__ void dinv_kernel(int N) {
    int i = blockIdx.x * blockDim.x + threadIdx.x;
    if (i < N) {
        // +1 for the self-loop; degree then always > 0
        g_dinv[i] = rsqrtf((float)(g_deg[i] + 1));
    }
}

// ---------------------------------------------------------------------------
// GEMM. LAYER 0: g_h = Xext @ W,        OUT = g_out1
//       LAYER 1: g_h = relu(g_out1)@W,  OUT = g_out2
// Epilogue initializes OUT[n,f] = bias[f] + g_h[n,f]*dinv[n]^2 (self-loop+bias)
// ---------------------------------------------------------------------------
template <int LAYER>
__global__ __launch_bounds__(256)
void gemm_kernel(const float* __restrict__ Xext, const float* __restrict__ W,
                 const float* __restrict__ bias, int N) {
    __shared__ float As[BM][BK];      // 64x16
    __shared__ float Bs[BK][BN];      // 16x128

    const float* X = (LAYER == 0) ? Xext : g_out1;
    float* OUT = (LAYER == 0) ? g_out1 : g_out2;

    const int tid = threadIdx.x;
    const int tx = tid & 31;          // 32 col-groups of 4
    const int ty = tid >> 5;          // 8 row-groups of 8
    const int row0 = blockIdx.x * BM + ty * 8;
    const int col0 = tx * 4;

    float acc[8][4];
#pragma unroll
    for (int i = 0; i < 8; i++)
#pragma unroll
        for (int j = 0; j < 4; j++) acc[i][j] = 0.0f;

    for (int k0 = 0; k0 < F; k0 += BK) {
        // A tile: 64x16 floats = 1024 = 256 threads * 4 (float4)
        {
            int idx = tid * 4;
            int r = idx >> 4;
            int c = idx & 15;
            int grow = blockIdx.x * BM + r;
            float4 v = make_float4(0.f, 0.f, 0.f, 0.f);
            if (grow < N) {
                v = *(const float4*)(X + (size_t)grow * F + k0 + c);
                if (LAYER == 1) {
                    v.x = fmaxf(v.x, 0.f); v.y = fmaxf(v.y, 0.f);
                    v.z = fmaxf(v.z, 0.f); v.w = fmaxf(v.w, 0.f);
                }
            }
            As[r][c] = v.x; As[r][c + 1] = v.y; As[r][c + 2] = v.z; As[r][c + 3] = v.w;
        }
        // B tile: 16x128 floats = 2048 = 256 threads * 8 (2x float4)
        {
#pragma unroll
            for (int l = 0; l < 2; l++) {
                int idx = tid * 4 + l * 1024;
                int r = idx >> 7;
                int c = idx & 127;
                *(float4*)&Bs[r][c] = *(const float4*)(W + (size_t)(k0 + r) * F + c);
            }
        }
        __syncthreads();

#pragma unroll
        for (int kk = 0; kk < BK; kk++) {
            float a[8], b[4];
#pragma unroll
            for (int i = 0; i < 8; i++) a[i] = As[ty * 8 + i][kk];
#pragma unroll
            for (int j = 0; j < 4; j++) b[j] = Bs[kk][col0 + j];
#pragma unroll
            for (int i = 0; i < 8; i++)
#pragma unroll
                for (int j = 0; j < 4; j++) acc[i][j] = fmaf(a[i], b[j], acc[i][j]);
        }
        __syncthreads();
    }

    float bv[4];
#pragma unroll
    for (int j = 0; j < 4; j++) bv[j] = bias[col0 + j];

#pragma unroll
    for (int i = 0; i < 8; i++) {
        int n = row0 + i;
        if (n < N) {
            float d = g_dinv[n];
            float d2 = d * d;
            float4 hv = make_float4(acc[i][0], acc[i][1], acc[i][2], acc[i][3]);
            *(float4*)(g_h + (size_t)n * F + col0) = hv;
            float4 ov = make_float4(bv[0] + hv.x * d2, bv[1] + hv.y * d2,
                                    bv[2] + hv.z * d2, bv[3] + hv.w * d2);
            *(float4*)(OUT + (size_t)n * F + col0) = ov;
        }
    }
}

// ---------------------------------------------------------------------------
// Edge scatter: one warp per edge, lane handles a float4 slice.
// OUT[dst] += g_h[src] * dinv[src]*dinv[dst]   (OUT is device scratch only)
// ---------------------------------------------------------------------------
template <int LAYER>
__global__ __launch_bounds__(256)
void scatter_kernel(const int* __restrict__ ei, int E, int N) {
    int gwarp = (blockIdx.x * blockDim.x + threadIdx.x) >> 5;
    int lane = threadIdx.x & 31;
    if (gwarp >= E) return;
    int is64 = g_is64;
    int src = edge_at(ei, gwarp, is64);
    int dst = edge_at(ei, (long long)E + gwarp, is64);
    if ((unsigned)src >= (unsigned)N || (unsigned)dst >= (unsigned)N) return;
    float norm = g_dinv[src] * g_dinv[dst];
    float4 v = *(const float4*)(g_h + (size_t)src * F + lane * 4);
    float* OUT = (LAYER == 0) ? g_out1 : g_out2;
    float* o = OUT + (size_t)dst * F + lane * 4;
    atomicAdd(o + 0, v.x * norm);
    atomicAdd(o + 1, v.y * norm);
    atomicAdd(o + 2, v.z * norm);
    atomicAdd(o + 3, v.w * norm);
}

// ---------------------------------------------------------------------------
// Final: d_out = relu(g_out2). Plain stores only into the harness buffer.
// ---------------------------------------------------------------------------
__global__ void final_relu_kernel(float* __restrict__ Y, int n4) {
    int i = blockIdx.x * blockDim.x + threadIdx.x;
    if (i < n4) {
        float4 v = *(const float4*)(g_out2 + (size_t)i * 4);
        v.x = fmaxf(v.x, 0.f); v.y = fmaxf(v.y, 0.f);
        v.z = fmaxf(v.z, 0.f); v.w = fmaxf(v.w, 0.f);
        *(float4*)(Y + (size_t)i * 4) = v;
    }
}

extern "C" void kernel_launch(void* const* d_in, const int* in_sizes, int n_in,
                              void* d_out, int out_size) {
    const float* x = (const float*)d_in[0];
    const int* ei = (const int*)d_in[1];   // int32 OR int64 — detected on device
    const float* W1 = (const float*)d_in[2];
    const float* b1 = (const float*)d_in[3];
    const float* W2 = (const float*)d_in[4];
    const float* b2 = (const float*)d_in[5];
    float* out = (float*)d_out;

    int N = in_sizes[0] / F;
    int E = in_sizes[1] / 2;

    // --- dtype detection + degree/normalization (shared by both layers) ---
    detect_kernel<<<1, 32>>>(ei);
    zero_deg_kernel<<<(N + 255) / 256, 256>>>(N);
    count_deg_kernel<<<(E + 255) / 256, 256>>>(ei, E, N);
    dinv_kernel<<<(N + 255) / 256, 256>>>(N);

    int gemm_grid = (N + BM - 1) / BM;
    int scat_grid = (E * 32 + 255) / 256;

    // --- layer 1: h = x@W1; out1 = b1 + self-loop; out1 += edge messages ---
    gemm_kernel<0><<<gemm_grid, 256>>>(x, W1, b1, N);
    scatter_kernel<0><<<scat_grid, 256>>>(ei, E, N);

    // --- layer 2: h = relu(out1)@W2; out2 = b2 + self-loop; out2 += edges ---
    gemm_kernel<1><<<gemm_grid, 256>>>(nullptr, W2, b2, N);
    scatter_kernel<1><<<scat_grid, 256>>>(ei, E, N);

    // --- d_out = relu(out2), plain stores ---
    int n4 = N * F / 4;
    final_relu_kernel<<<(n4 + 255) / 256, 256>>>(out, n4);
}

// round 5
// speedup vs baseline: 3.3409x; 3.3409x over previous
#include <cuda_runtime.h>
#include <cuda_bf16.h>

#define F 128
#define MAXN 50048
#define MAXE 1048576

#define BM 64
#define BK 16

// Device-global scratch. Never referenced from host; all atomics target these.
__device__ __align__(16) float g_h[(size_t)MAXN * F];     // GEMM out / gather src
__device__ __align__(16) float g_out1[(size_t)MAXN * F];  // layer-1 result
__device__ float g_dinv[MAXN];
__device__ int   g_deg[MAXN];
__device__ int   g_off[MAXN + 1];   // CSR row offsets (by dst)
__device__ int   g_cur[MAXN];       // build cursors
__device__ int   g_csr_src[MAXE];   // src node per CSR slot
__device__ float g_csr_norm[MAXE];  // dinv[src]*dinv[dst] per CSR slot
__device__ int   g_is64;

// ---------------------------------------------------------------------------
// edge dtype detection (int64 little-endian => odd words of first entries = 0)
// ---------------------------------------------------------------------------
__global__ void detect_kernel(const int* __restrict__ ei32) {
    if (threadIdx.x == 0) {
        int is64 = 1;
        for (int k = 1; k < 128; k += 2)
            if (ei32[k] != 0) { is64 = 0; break; }
        g_is64 = is64;
    }
}

__device__ __forceinline__ int edge_at(const int* __restrict__ ei32,
                                       long long idx, int is64) {
    if (is64) return (int)__ldg(((const long long*)ei32) + idx);
    return __ldg(ei32 + idx);
}

// ---------------------------------------------------------------------------
// degree / normalization / CSR build
// ---------------------------------------------------------------------------
__global__ void zero_deg_kernel(int N) {
    int i = blockIdx.x * blockDim.x + threadIdx.x;
    if (i < N) g_deg[i] = 0;
}

__global__ void count_deg_kernel(const int* __restrict__ ei, int E, int N) {
    int e = blockIdx.x * blockDim.x + threadIdx.x;
    if (e < E) {
        int is64 = g_is64;
        int dst = edge_at(ei, (long long)E + e, is64);
        if ((unsigned)dst < (unsigned)N)
            atomicAdd(&g_deg[dst], 1);
    }
}

__global__ void dinv_kernel(int N) {
    int i = blockIdx.x * blockDim.x + threadIdx.x;
    if (i < N) g_dinv[i] = rsqrtf((float)(g_deg[i] + 1));  // +1 = self-loop
}

// Single-block exclusive scan of g_deg -> g_off (+ cursors). N <= MAXN.
__global__ __launch_bounds__(1024)
void scan_kernel(int N) {
    __shared__ int sums[1024];
    int t = threadIdx.x;
    int chunk = (N + 1023) / 1024;
    int lo = t * chunk;
    int hi = min(lo + chunk, N);
    int s = 0;
    for (int i = lo; i < hi; i++) s += g_deg[i];
    sums[t] = s;
    __syncthreads();
    // Hillis-Steele inclusive scan
    for (int d = 1; d < 1024; d <<= 1) {
        int v = (t >= d) ? sums[t - d] : 0;
        __syncthreads();
        sums[t] += v;
        __syncthreads();
    }
    int base = (t == 0) ? 0 : sums[t - 1];
    for (int i = lo; i < hi; i++) {
        g_off[i] = base;
        g_cur[i] = base;
        base += g_deg[i];
    }
    if (hi == N && lo <= N) g_off[N] = base;
}

__global__ void build_csr_kernel(const int* __restrict__ ei, int E, int N) {
    int e = blockIdx.x * blockDim.x + threadIdx.x;
    if (e >= E) return;
    int is64 = g_is64;
    int src = edge_at(ei, e, is64);
    int dst = edge_at(ei, (long long)E + e, is64);
    if ((unsigned)src >= (unsigned)N || (unsigned)dst >= (unsigned)N) return;
    int pos = atomicAdd(&g_cur[dst], 1);
    g_csr_src[pos] = src;
    g_csr_norm[pos] = g_dinv[src] * g_dinv[dst];
}

// ---------------------------------------------------------------------------
// GEMM. LAYER 0: g_h = Xext @ W ;  LAYER 1: g_h = relu(g_out1) @ W
// Writes only g_h (self-loop/bias handled in the gather).
// ---------------------------------------------------------------------------
template <int LAYER>
__global__ __launch_bounds__(256)
void gemm_kernel(const float* __restrict__ Xext, const float* __restrict__ W,
                 int N) {
    __shared__ float As[BM][BK];      // 64x16
    __shared__ float Bs[BK][F];       // 16x128

    const float* X = (LAYER == 0) ? Xext : g_out1;

    const int tid = threadIdx.x;
    const int tx = tid & 31;
    const int ty = tid >> 5;
    const int row0 = blockIdx.x * BM + ty * 8;
    const int col0 = tx * 4;

    float acc[8][4];
#pragma unroll
    for (int i = 0; i < 8; i++)
#pragma unroll
        for (int j = 0; j < 4; j++) acc[i][j] = 0.0f;

    for (int k0 = 0; k0 < F; k0 += BK) {
        {   // A tile: 64x16 = 256 threads * float4
            int idx = tid * 4;
            int r = idx >> 4;
            int c = idx & 15;
            int grow = blockIdx.x * BM + r;
            float4 v = make_float4(0.f, 0.f, 0.f, 0.f);
            if (grow < N) {
                v = *(const float4*)(X + (size_t)grow * F + k0 + c);
                if (LAYER == 1) {
                    v.x = fmaxf(v.x, 0.f); v.y = fmaxf(v.y, 0.f);
                    v.z = fmaxf(v.z, 0.f); v.w = fmaxf(v.w, 0.f);
                }
            }
            As[r][c] = v.x; As[r][c + 1] = v.y; As[r][c + 2] = v.z; As[r][c + 3] = v.w;
        }
        {   // B tile: 16x128 = 256 threads * 2 float4
#pragma unroll
            for (int l = 0; l < 2; l++) {
                int idx = tid * 4 + l * 1024;
                int r = idx >> 7;
                int c = idx & 127;
                *(float4*)&Bs[r][c] = *(const float4*)(W + (size_t)(k0 + r) * F + c);
            }
        }
        __syncthreads();

#pragma unroll
        for (int kk = 0; kk < BK; kk++) {
            float a[8], b[4];
#pragma unroll
            for (int i = 0; i < 8; i++) a[i] = As[ty * 8 + i][kk];
#pragma unroll
            for (int j = 0; j < 4; j++) b[j] = Bs[kk][col0 + j];
#pragma unroll
            for (int i = 0; i < 8; i++)
#pragma unroll
                for (int j = 0; j < 4; j++) acc[i][j] = fmaf(a[i], b[j], acc[i][j]);
        }
        __syncthreads();
    }

#pragma unroll
    for (int i = 0; i < 8; i++) {
        int n = row0 + i;
        if (n < N)
            *(float4*)(g_h + (size_t)n * F + col0) =
                make_float4(acc[i][0], acc[i][1], acc[i][2], acc[i][3]);
    }
}

// ---------------------------------------------------------------------------
// Gather aggregation: one warp per dst node, zero atomics.
//   out[n] = bias + g_h[n]*dinv[n]^2 + sum_{e in CSR[n]} g_h[src_e]*norm_e
// LAYER 0 -> g_out1 (raw); LAYER 1 -> out_ext with ReLU (final output).
// ---------------------------------------------------------------------------
template <int LAYER>
__global__ __launch_bounds__(256)
void gather_kernel(const float* __restrict__ bias, float* __restrict__ out_ext,
                   int N) {
    int w = (blockIdx.x * blockDim.x + threadIdx.x) >> 5;
    int lane = threadIdx.x & 31;
    if (w >= N) return;

    const int c = lane * 4;
    const int off = g_off[w];
    const int end = g_off[w + 1];

    float d = g_dinv[w];
    float d2 = d * d;
    float4 hv = *(const float4*)(g_h + (size_t)w * F + c);
    float4 bv = *(const float4*)(bias + c);
    float4 acc = make_float4(bv.x + hv.x * d2, bv.y + hv.y * d2,
                             bv.z + hv.z * d2, bv.w + hv.w * d2);

    int e = off;
    // 2-wide unroll for memory-level parallelism
    for (; e + 1 < end; e += 2) {
        int s0 = g_csr_src[e];
        int s1 = g_csr_src[e + 1];
        float n0 = g_csr_norm[e];
        float n1 = g_csr_norm[e + 1];
        float4 v0 = *(const float4*)(g_h + (size_t)s0 * F + c);
        float4 v1 = *(const float4*)(g_h + (size_t)s1 * F + c);
        acc.x += v0.x * n0; acc.y += v0.y * n0; acc.z += v0.z * n0; acc.w += v0.w * n0;
        acc.x += v1.x * n1; acc.y += v1.y * n1; acc.z += v1.z * n1; acc.w += v1.w * n1;
    }
    if (e < end) {
        int s0 = g_csr_src[e];
        float n0 = g_csr_norm[e];
        float4 v0 = *(const float4*)(g_h + (size_t)s0 * F + c);
        acc.x += v0.x * n0; acc.y += v0.y * n0; acc.z += v0.z * n0; acc.w += v0.w * n0;
    }

    if (LAYER == 1) {
        acc.x = fmaxf(acc.x, 0.f); acc.y = fmaxf(acc.y, 0.f);
        acc.z = fmaxf(acc.z, 0.f); acc.w = fmaxf(acc.w, 0.f);
        *(float4*)(out_ext + (size_t)w * F + c) = acc;   // plain STG to d_out
    } else {
        *(float4*)(g_out1 + (size_t)w * F + c) = acc;
    }
}

extern "C" void kernel_launch(void* const* d_in, const int* in_sizes, int n_in,
                              void* d_out, int out_size) {
    const float* x = (const float*)d_in[0];
    const int* ei = (const int*)d_in[1];   // int32 or int64, detected on device
    const float* W1 = (const float*)d_in[2];
    const float* b1 = (const float*)d_in[3];
    const float* W2 = (const float*)d_in[4];
    const float* b2 = (const float*)d_in[5];
    float* out = (float*)d_out;

    int N = in_sizes[0] / F;
    int E = in_sizes[1] / 2;

    // --- CSR build (shared by both layers) ---
    detect_kernel<<<1, 32>>>(ei);
    zero_deg_kernel<<<(N + 255) / 256, 256>>>(N);
    count_deg_kernel<<<(E + 255) / 256, 256>>>(ei, E, N);
    dinv_kernel<<<(N + 255) / 256, 256>>>(N);
    scan_kernel<<<1, 1024>>>(N);
    build_csr_kernel<<<(E + 255) / 256, 256>>>(ei, E, N);

    int gemm_grid = (N + BM - 1) / BM;
    int gath_grid = (N * 32 + 255) / 256;

    // --- layer 1 ---
    gemm_kernel<0><<<gemm_grid, 256>>>(x, W1, N);
    gather_kernel<0><<<gath_grid, 256>>>(b1, nullptr, N);

    // --- layer 2 (relu fused into gather epilogue, direct store to d_out) ---
    gemm_kernel<1><<<gemm_grid, 256>>>(nullptr, W2, N);
    gather_kernel<1><<<gath_grid, 256>>>(b2, out, N);
}

// round 6
// speedup vs baseline: 4.2460x; 1.2709x over previous
#include <cuda_runtime.h>
#include <cuda_bf16.h>
#include <cstdint>

#define F 128
#define MAXN 50048
#define MAXE 1048576

// Device-global scratch. Never referenced from host; all atomics target these.
__device__ __align__(16) float g_h[(size_t)MAXN * F];     // GEMM out / gather src
__device__ __align__(16) float g_out1[(size_t)MAXN * F];  // layer-1 result
__device__ float g_dinv[MAXN];
__device__ int   g_deg[MAXN];
__device__ int   g_off[MAXN + 1];   // CSR row offsets (by dst)
__device__ int   g_cur[MAXN];       // build cursors
__device__ int   g_csr_src[MAXE];   // src node per CSR slot
__device__ float g_csr_norm[MAXE];  // dinv[src]*dinv[dst] per CSR slot
__device__ int   g_is64;

// ---------------------------------------------------------------------------
// edge dtype detection (int64 little-endian => odd words of first entries = 0)
// ---------------------------------------------------------------------------
__global__ void detect_kernel(const int* __restrict__ ei32) {
    if (threadIdx.x == 0) {
        int is64 = 1;
        for (int k = 1; k < 128; k += 2)
            if (ei32[k] != 0) { is64 = 0; break; }
        g_is64 = is64;
    }
}

__device__ __forceinline__ int edge_at(const int* __restrict__ ei32,
                                       long long idx, int is64) {
    if (is64) return (int)__ldg(((const long long*)ei32) + idx);
    return __ldg(ei32 + idx);
}

// ---------------------------------------------------------------------------
// degree / normalization / CSR build
// ---------------------------------------------------------------------------
__global__ void zero_deg_kernel(int N) {
    int i = blockIdx.x * blockDim.x + threadIdx.x;
    if (i < N) g_deg[i] = 0;
}

__global__ void count_deg_kernel(const int* __restrict__ ei, int E, int N) {
    int e = blockIdx.x * blockDim.x + threadIdx.x;
    if (e < E) {
        int is64 = g_is64;
        int dst = edge_at(ei, (long long)E + e, is64);
        if ((unsigned)dst < (unsigned)N)
            atomicAdd(&g_deg[dst], 1);
    }
}

__global__ void dinv_kernel(int N) {
    int i = blockIdx.x * blockDim.x + threadIdx.x;
    if (i < N) g_dinv[i] = rsqrtf((float)(g_deg[i] + 1));  // +1 = self-loop
}

// Single-block exclusive scan of g_deg -> g_off (+ cursors). N <= MAXN.
__global__ __launch_bounds__(1024)
void scan_kernel(int N) {
    __shared__ int sums[1024];
    int t = threadIdx.x;
    int chunk = (N + 1023) / 1024;
    int lo = t * chunk;
    int hi = min(lo + chunk, N);
    int s = 0;
    for (int i = lo; i < hi; i++) s += g_deg[i];
    sums[t] = s;
    __syncthreads();
    for (int d = 1; d < 1024; d <<= 1) {
        int v = (t >= d) ? sums[t - d] : 0;
        __syncthreads();
        sums[t] += v;
        __syncthreads();
    }
    int base = (t == 0) ? 0 : sums[t - 1];
    for (int i = lo; i < hi; i++) {
        g_off[i] = base;
        g_cur[i] = base;
        base += g_deg[i];
    }
    if (hi == N && lo <= N) g_off[N] = base;
}

__global__ void build_csr_kernel(const int* __restrict__ ei, int E, int N) {
    int e = blockIdx.x * blockDim.x + threadIdx.x;
    if (e >= E) return;
    int is64 = g_is64;
    int src = edge_at(ei, e, is64);
    int dst = edge_at(ei, (long long)E + e, is64);
    if ((unsigned)src >= (unsigned)N || (unsigned)dst >= (unsigned)N) return;
    int pos = atomicAdd(&g_cur[dst], 1);
    g_csr_src[pos] = src;
    g_csr_norm[pos] = g_dinv[src] * g_dinv[dst];
}

// ---------------------------------------------------------------------------
// TF32 tensor-core GEMM.  LAYER 0: g_h = Xext@W ; LAYER 1: g_h = relu(g_out1)@W
// BM=128, BN=128(=F), BK=32.  256 thr = 8 warps in 4x2; warp tile 32x64.
// ---------------------------------------------------------------------------
__device__ __forceinline__ uint32_t f2tf32(float f) {
    uint32_t r;
    asm("cvt.rna.tf32.f32 %0, %1;" : "=r"(r) : "f"(f));
    return r;
}

__device__ __forceinline__ void mma_tf32(float* c, const uint32_t* a,
                                         const uint32_t* b) {
    asm volatile(
        "mma.sync.aligned.m16n8k8.row.col.f32.tf32.tf32.f32 "
        "{%0,%1,%2,%3}, {%4,%5,%6,%7}, {%8,%9}, {%0,%1,%2,%3};\n"
        : "+f"(c[0]), "+f"(c[1]), "+f"(c[2]), "+f"(c[3])
        : "r"(a[0]), "r"(a[1]), "r"(a[2]), "r"(a[3]), "r"(b[0]), "r"(b[1]));
}

template <int LAYER>
__global__ __launch_bounds__(256)
void gemm_kernel(const float* __restrict__ Xext, const float* __restrict__ W,
                 int N) {
    // pads: 33 % 32 == 1 and 136 % 32 == 8 -> conflict-free fragment loads
    __shared__ uint32_t As[128][33];
    __shared__ uint32_t Bs[32][136];

    const float* X = (LAYER == 0) ? Xext : g_out1;

    const int tid = threadIdx.x;
    const int wid = tid >> 5;
    const int lane = tid & 31;
    const int wm = wid & 3;            // 0..3 -> 32-row band
    const int wn = wid >> 2;           // 0..1 -> 64-col band
    const int row0 = blockIdx.x * 128;

    float acc[2][8][4];
#pragma unroll
    for (int mt = 0; mt < 2; mt++)
#pragma unroll
        for (int j = 0; j < 8; j++)
#pragma unroll
            for (int q = 0; q < 4; q++) acc[mt][j][q] = 0.0f;

    for (int kc = 0; kc < 4; kc++) {
        const int k0 = kc * 32;
        // --- A tile: 128x32 floats = 1024 float4 = 256 thr * 4 ---
#pragma unroll
        for (int l = 0; l < 4; l++) {
            int f4 = tid + l * 256;
            int r = f4 >> 3;           // 8 float4 per row
            int c4 = (f4 & 7) * 4;
            int grow = row0 + r;
            float4 v = make_float4(0.f, 0.f, 0.f, 0.f);
            if (grow < N) {
                v = *(const float4*)(X + (size_t)grow * F + k0 + c4);
                if (LAYER == 1) {
                    v.x = fmaxf(v.x, 0.f); v.y = fmaxf(v.y, 0.f);
                    v.z = fmaxf(v.z, 0.f); v.w = fmaxf(v.w, 0.f);
                }
            }
            As[r][c4] = f2tf32(v.x); As[r][c4 + 1] = f2tf32(v.y);
            As[r][c4 + 2] = f2tf32(v.z); As[r][c4 + 3] = f2tf32(v.w);
        }
        // --- B tile: 32x128 floats = 1024 float4 = 256 thr * 4 ---
#pragma unroll
        for (int l = 0; l < 4; l++) {
            int f4 = tid + l * 256;
            int r = f4 >> 5;           // 32 float4 per row
            int c4 = (f4 & 31) * 4;
            float4 v = *(const float4*)(W + (size_t)(k0 + r) * F + c4);
            Bs[r][c4] = f2tf32(v.x); Bs[r][c4 + 1] = f2tf32(v.y);
            Bs[r][c4 + 2] = f2tf32(v.z); Bs[r][c4 + 3] = f2tf32(v.w);
        }
        __syncthreads();

#pragma unroll
        for (int ks = 0; ks < 4; ks++) {
            const int kk = ks * 8;
            const int g = lane >> 2;     // 0..7
            const int r4 = lane & 3;     // 0..3
            uint32_t a[2][4];
#pragma unroll
            for (int mt = 0; mt < 2; mt++) {
                int ar = wm * 32 + mt * 16 + g;
                a[mt][0] = As[ar][kk + r4];
                a[mt][1] = As[ar + 8][kk + r4];
                a[mt][2] = As[ar][kk + r4 + 4];
                a[mt][3] = As[ar + 8][kk + r4 + 4];
            }
            uint32_t b[8][2];
#pragma unroll
            for (int j = 0; j < 8; j++) {
                int bc = wn * 64 + j * 8 + g;
                b[j][0] = Bs[kk + r4][bc];
                b[j][1] = Bs[kk + r4 + 4][bc];
            }
#pragma unroll
            for (int mt = 0; mt < 2; mt++)
#pragma unroll
                for (int j = 0; j < 8; j++)
                    mma_tf32(acc[mt][j], a[mt], b[j]);
        }
        __syncthreads();
    }

    // epilogue: c0,c1 -> (row, 2c), (row, 2c+1); c2,c3 -> row+8
    const int g = lane >> 2;
    const int r4 = lane & 3;
#pragma unroll
    for (int mt = 0; mt < 2; mt++) {
        int row = row0 + wm * 32 + mt * 16 + g;
#pragma unroll
        for (int j = 0; j < 8; j++) {
            int col = wn * 64 + j * 8 + r4 * 2;
            if (row < N)
                *(float2*)(g_h + (size_t)row * F + col) =
                    make_float2(acc[mt][j][0], acc[mt][j][1]);
            if (row + 8 < N)
                *(float2*)(g_h + (size_t)(row + 8) * F + col) =
                    make_float2(acc[mt][j][2], acc[mt][j][3]);
        }
    }
}

// ---------------------------------------------------------------------------
// Gather aggregation: one warp per dst node, zero atomics.
//   out[n] = bias + g_h[n]*dinv[n]^2 + sum_{e in CSR[n]} g_h[src_e]*norm_e
// ---------------------------------------------------------------------------
template <int LAYER>
__global__ __launch_bounds__(256)
void gather_kernel(const float* __restrict__ bias, float* __restrict__ out_ext,
                   int N) {
    int w = (blockIdx.x * blockDim.x + threadIdx.x) >> 5;
    int lane = threadIdx.x & 31;
    if (w >= N) return;

    const int c = lane * 4;
    const int off = g_off[w];
    const int end = g_off[w + 1];

    float d = g_dinv[w];
    float d2 = d * d;
    float4 hv = *(const float4*)(g_h + (size_t)w * F + c);
    float4 bv = *(const float4*)(bias + c);
    float4 acc = make_float4(bv.x + hv.x * d2, bv.y + hv.y * d2,
                             bv.z + hv.z * d2, bv.w + hv.w * d2);

    int e = off;
    for (; e + 3 < end; e += 4) {
        int s0 = g_csr_src[e], s1 = g_csr_src[e + 1];
        int s2 = g_csr_src[e + 2], s3 = g_csr_src[e + 3];
        float n0 = g_csr_norm[e], n1 = g_csr_norm[e + 1];
        float n2 = g_csr_norm[e + 2], n3 = g_csr_norm[e + 3];
        float4 v0 = *(const float4*)(g_h + (size_t)s0 * F + c);
        float4 v1 = *(const float4*)(g_h + (size_t)s1 * F + c);
        float4 v2 = *(const float4*)(g_h + (size_t)s2 * F + c);
        float4 v3 = *(const float4*)(g_h + (size_t)s3 * F + c);
        acc.x += v0.x * n0; acc.y += v0.y * n0; acc.z += v0.z * n0; acc.w += v0.w * n0;
        acc.x += v1.x * n1; acc.y += v1.y * n1; acc.z += v1.z * n1; acc.w += v1.w * n1;
        acc.x += v2.x * n2; acc.y += v2.y * n2; acc.z += v2.z * n2; acc.w += v2.w * n2;
        acc.x += v3.x * n3; acc.y += v3.y * n3; acc.z += v3.z * n3; acc.w += v3.w * n3;
    }
    for (; e < end; e++) {
        int s0 = g_csr_src[e];
        float n0 = g_csr_norm[e];
        float4 v0 = *(const float4*)(g_h + (size_t)s0 * F + c);
        acc.x += v0.x * n0; acc.y += v0.y * n0; acc.z += v0.z * n0; acc.w += v0.w * n0;
    }

    if (LAYER == 1) {
        acc.x = fmaxf(acc.x, 0.f); acc.y = fmaxf(acc.y, 0.f);
        acc.z = fmaxf(acc.z, 0.f); acc.w = fmaxf(acc.w, 0.f);
        *(float4*)(out_ext + (size_t)w * F + c) = acc;   // plain STG to d_out
    } else {
        *(float4*)(g_out1 + (size_t)w * F + c) = acc;
    }
}

extern "C" void kernel_launch(void* const* d_in, const int* in_sizes, int n_in,
                              void* d_out, int out_size) {
    const float* x = (const float*)d_in[0];
    const int* ei = (const int*)d_in[1];   // int32 or int64, detected on device
    const float* W1 = (const float*)d_in[2];
    const float* b1 = (const float*)d_in[3];
    const float* W2 = (const float*)d_in[4];
    const float* b2 = (const float*)d_in[5];
    float* out = (float*)d_out;

    int N = in_sizes[0] / F;
    int E = in_sizes[1] / 2;

    // --- CSR build (shared by both layers) ---
    detect_kernel<<<1, 32>>>(ei);
    zero_deg_kernel<<<(N + 255) / 256, 256>>>(N);
    count_deg_kernel<<<(E + 255) / 256, 256>>>(ei, E, N);
    dinv_kernel<<<(N + 255) / 256, 256>>>(N);
    scan_kernel<<<1, 1024>>>(N);
    build_csr_kernel<<<(E + 255) / 256, 256>>>(ei, E, N);

    int gemm_grid = (N + 127) / 128;
    int gath_grid = (N * 32 + 255) / 256;

    // --- layer 1 ---
    gemm_kernel<0><<<gemm_grid, 256>>>(x, W1, N);
    gather_kernel<0><<<gath_grid, 256>>>(b1, nullptr, N);

    // --- layer 2 (relu fused into gather epilogue, direct store to d_out) ---
    gemm_kernel<1><<<gemm_grid, 256>>>(nullptr, W2, N);
    gather_kernel<1><<<gath_grid, 256>>>(b2, out, N);
}